// round 11
// baseline (speedup 1.0000x reference)
#include <cuda_runtime.h>
#include <cuda_bf16.h>
#include <cstdint>

// Complex attention, mma.sync bf16 3-term split, warp-specialized pipeline.
// B=8 H=8 S=1024 D=64.
// K1: attn=(q/8).k -> spill + per-(row,half) mag^2 min/max   [128q x 64k tiles]
// K2: row min/max reduce
// K3: normalize(attn) @ v                                    [64q x 64d tiles]
// 384 threads: warps 0-7 consumers (MMA), warps 8-11 producers (fill).

#define NKT 2
typedef unsigned long long u64;
typedef uint32_t u32;

__device__ float g_ar[(size_t)64 * 1024 * 1024];   // 256 MB
__device__ float g_ai[(size_t)64 * 1024 * 1024];   // 256 MB
__device__ float g_pmin[64 * 1024 * NKT];
__device__ float g_pmax[64 * 1024 * NKT];
__device__ float g_mn[64 * 1024];
__device__ float g_inv[64 * 1024];

__device__ __forceinline__ u32 smem_u32(const void* p) {
    u32 a;
    asm("{ .reg .u64 t; cvta.to.shared.u64 t, %1; cvt.u32.u64 %0, t; }"
        : "=r"(a) : "l"(p));
    return a;
}

#define SW128(x) ((x) ^ (((x) >> 3) & 0x70))
#define NEGS 0x80008000u
#define TB16 16384
#define TB8  8192

// Named barriers: FULL = 1+buf, EMPTY = 3+buf; all 384 threads counted.
#define BARSYNC(id) asm volatile("bar.sync %0, 384;" :: "r"(id) : "memory")
#define BARARV(id)  asm volatile("bar.arrive %0, 384;" :: "r"(id) : "memory")

__device__ __forceinline__ void ldmx4(u32* r, u32 a) {
    asm volatile("ldmatrix.sync.aligned.m8n8.x4.shared.b16 {%0,%1,%2,%3}, [%4];"
        : "=r"(r[0]), "=r"(r[1]), "=r"(r[2]), "=r"(r[3]) : "r"(a));
}
__device__ __forceinline__ void ldmx2(u32* r, u32 a) {
    asm volatile("ldmatrix.sync.aligned.m8n8.x2.shared.b16 {%0,%1}, [%2];"
        : "=r"(r[0]), "=r"(r[1]) : "r"(a));
}
__device__ __forceinline__ void ldmx2t(u32* r, u32 a) {
    asm volatile("ldmatrix.sync.aligned.m8n8.x2.trans.shared.b16 {%0,%1}, [%2];"
        : "=r"(r[0]), "=r"(r[1]) : "r"(a));
}
__device__ __forceinline__ void mma16816(float* c, const u32* a, const u32* b) {
    asm volatile("mma.sync.aligned.m16n8k16.row.col.f32.bf16.bf16.f32 "
        "{%0,%1,%2,%3}, {%4,%5,%6,%7}, {%8,%9}, {%0,%1,%2,%3};"
        : "+f"(c[0]), "+f"(c[1]), "+f"(c[2]), "+f"(c[3])
        : "r"(a[0]), "r"(a[1]), "r"(a[2]), "r"(a[3]), "r"(b[0]), "r"(b[1]));
}

// fp32 pair -> bf16 hi/lo pairs, SW128 layout (128B rows).
__device__ __forceinline__ void st_split2(char* hi, char* lo, int row, int cp, float2 v) {
    __nv_bfloat162 h = __float22bfloat162_rn(v);
    float2 hf = __bfloat1622float2(h);
    __nv_bfloat162 l = __float22bfloat162_rn(make_float2(v.x - hf.x, v.y - hf.y));
    u32 off = SW128((u32)(row * 128 + cp * 4));
    *(u32*)(hi + off) = *(u32*)&h;
    *(u32*)(lo + off) = *(u32*)&l;
}

// ---------------------------------------------------------------------------
// K1: QK. CTA covers 128q x (8 tiles of 64k). Q resident, K double-buffered.
// Consumers: 8 warps (4m x 2n), warp tile 32q x 32k per k-tile.
// attn_r = qr.kr - qi.ki ; attn_i = qr.ki + qi.kr
// ---------------------------------------------------------------------------
__global__ __launch_bounds__(384, 1) void qk_kernel(
    const float* __restrict__ qr, const float* __restrict__ qi,
    const float* __restrict__ kr, const float* __restrict__ ki)
{
    extern __shared__ __align__(128) char sm[];
    char* s_q  = sm;                 // 4 arrays x 16KB: qrh qrl qih qil
    char* s_kb = sm + 4 * TB16;      // 2 bufs x 4 arrays x 8KB: krh krl kih kil
    __shared__ float sMin[128][2], sMax[128][2];

    const int tid = threadIdx.x, wid = tid >> 5, lane = tid & 31;
    const int half = blockIdx.x, qt = blockIdx.y, bh = blockIdx.z;
    const int kt0 = half << 3;

    // ---- Q fill (all 384 threads) ----
    {
        const size_t qbase = ((size_t)((bh << 10) + (qt << 7))) << 6;
        for (int i = tid; i < 4096; i += 384) {
            int row = i >> 5, cp = i & 31;
            float2 a = *(const float2*)(qr + qbase + (row << 6) + cp * 2);
            float2 b = *(const float2*)(qi + qbase + (row << 6) + cp * 2);
            a.x *= 0.125f; a.y *= 0.125f;
            b.x *= 0.125f; b.y *= 0.125f;
            st_split2(s_q, s_q + TB16, row, cp, a);
            st_split2(s_q + 2 * TB16, s_q + 3 * TB16, row, cp, b);
        }
    }
    __syncthreads();

    if (wid < 8) {
        // ================= CONSUMERS =================
        const int wm = wid >> 1, wn = wid & 1;
        const int g = lane >> 2, tg = lane & 3;
        const u32 uq0 = smem_u32(s_q), uq1 = uq0 + TB16;
        const u32 uq2 = uq0 + 2 * TB16, uq3 = uq0 + 3 * TB16;
        const u32 a_row = (u32)(wm * 32 + (lane & 15));
        const u32 a_cb  = (u32)((lane >> 4) * 16);
        const u32 b_row = (u32)(wn * 32 + (lane & 7));
        const u32 b_cb  = (u32)(((lane >> 3) & 1) * 16);

        float rmn[4] = {3.4e38f, 3.4e38f, 3.4e38f, 3.4e38f};
        float rmx[4] = {0.f, 0.f, 0.f, 0.f};

        #pragma unroll 1
        for (int t = 0; t < 8; ++t) {
            const int b = t & 1;
            const int kt = kt0 + t;
            BARSYNC(1 + b);
            const u32 ukb = smem_u32(s_kb + b * (4 * TB8));

            float accR[2][4][4] = {}, accI[2][4][4] = {};
            #pragma unroll
            for (int kb = 0; kb < 4; ++kb) {
                u32 Aqrh[2][4], Aqrl[2][4], Aqih[2][4], Aqil[2][4];
                #pragma unroll
                for (int mb = 0; mb < 2; ++mb) {
                    u32 off = SW128((a_row + mb * 16) * 128 + kb * 32 + a_cb);
                    ldmx4(Aqrh[mb], uq0 + off);
                    ldmx4(Aqrl[mb], uq1 + off);
                    ldmx4(Aqih[mb], uq2 + off);
                    ldmx4(Aqil[mb], uq3 + off);
                }
                #pragma unroll
                for (int nb = 0; nb < 4; ++nb) {
                    u32 off = SW128((b_row + nb * 8) * 128 + kb * 32 + b_cb);
                    u32 Bkrh[2], Bkrl[2], Bkih[2], Bkil[2];
                    ldmx2(Bkrh, ukb + off);
                    ldmx2(Bkrl, ukb + TB8 + off);
                    ldmx2(Bkih, ukb + 2 * TB8 + off);
                    ldmx2(Bkil, ukb + 3 * TB8 + off);
                    u32 Bknh[2] = { Bkih[0] ^ NEGS, Bkih[1] ^ NEGS };
                    u32 Bknl[2] = { Bkil[0] ^ NEGS, Bkil[1] ^ NEGS };
                    #pragma unroll
                    for (int mb = 0; mb < 2; ++mb) {
                        mma16816(accR[mb][nb], Aqrh[mb], Bkrh);
                        mma16816(accR[mb][nb], Aqrh[mb], Bkrl);
                        mma16816(accR[mb][nb], Aqrl[mb], Bkrh);
                        mma16816(accR[mb][nb], Aqih[mb], Bknh);
                        mma16816(accR[mb][nb], Aqih[mb], Bknl);
                        mma16816(accR[mb][nb], Aqil[mb], Bknh);
                        mma16816(accI[mb][nb], Aqrh[mb], Bkih);
                        mma16816(accI[mb][nb], Aqrh[mb], Bkil);
                        mma16816(accI[mb][nb], Aqrl[mb], Bkih);
                        mma16816(accI[mb][nb], Aqih[mb], Bkrh);
                        mma16816(accI[mb][nb], Aqih[mb], Bkrl);
                        mma16816(accI[mb][nb], Aqil[mb], Bkrh);
                    }
                }
            }
            BARARV(3 + b);   // K buffer b free for producers

            // epilogue: store attn + accumulate row mag^2 min/max in regs
            #pragma unroll
            for (int mb = 0; mb < 2; ++mb)
                #pragma unroll
                for (int hf = 0; hf < 2; ++hf) {
                    int rl = wm * 32 + mb * 16 + hf * 8 + g;
                    size_t ab = (((size_t)((bh << 10) + (qt << 7) + rl)) << 10)
                              + (kt << 6) + wn * 32 + tg * 2;
                    float mn = rmn[mb * 2 + hf], mx = rmx[mb * 2 + hf];
                    #pragma unroll
                    for (int nb = 0; nb < 4; ++nb) {
                        float x0 = accR[mb][nb][hf * 2], x1 = accR[mb][nb][hf * 2 + 1];
                        float y0 = accI[mb][nb][hf * 2], y1 = accI[mb][nb][hf * 2 + 1];
                        *(float2*)(g_ar + ab + nb * 8) = make_float2(x0, x1);
                        *(float2*)(g_ai + ab + nb * 8) = make_float2(y0, y1);
                        float m0 = x0 * x0 + y0 * y0, m1 = x1 * x1 + y1 * y1;
                        mn = fminf(mn, fminf(m0, m1));
                        mx = fmaxf(mx, fmaxf(m0, m1));
                    }
                    rmn[mb * 2 + hf] = mn; rmx[mb * 2 + hf] = mx;
                }
        }

        // final min/max reduce
        #pragma unroll
        for (int s = 0; s < 4; ++s) {
            rmn[s] = fminf(rmn[s], __shfl_xor_sync(0xffffffffu, rmn[s], 1));
            rmn[s] = fminf(rmn[s], __shfl_xor_sync(0xffffffffu, rmn[s], 2));
            rmx[s] = fmaxf(rmx[s], __shfl_xor_sync(0xffffffffu, rmx[s], 1));
            rmx[s] = fmaxf(rmx[s], __shfl_xor_sync(0xffffffffu, rmx[s], 2));
        }
        if (tg == 0) {
            #pragma unroll
            for (int mb = 0; mb < 2; ++mb)
                #pragma unroll
                for (int hf = 0; hf < 2; ++hf) {
                    int rl = wm * 32 + mb * 16 + hf * 8 + g;
                    sMin[rl][wn] = rmn[mb * 2 + hf];
                    sMax[rl][wn] = rmx[mb * 2 + hf];
                }
        }
    } else {
        // ================= PRODUCERS =================
        const int ptid = tid - 256;
        const int cp = ptid & 31, r0 = ptid >> 5;
        #pragma unroll 1
        for (int t = 0; t < 8; ++t) {
            const int b = t & 1;
            if (t >= 2) BARSYNC(3 + b);
            const size_t kbase = ((size_t)((bh << 10) + ((kt0 + t) << 6))) << 6;
            char* kb = s_kb + b * (4 * TB8);
            #pragma unroll
            for (int it = 0; it < 16; ++it) {
                int row = r0 + (it << 2);
                float2 c = *(const float2*)(kr + kbase + (row << 6) + cp * 2);
                float2 d = *(const float2*)(ki + kbase + (row << 6) + cp * 2);
                st_split2(kb, kb + TB8, row, cp, c);
                st_split2(kb + 2 * TB8, kb + 3 * TB8, row, cp, d);
            }
            BARARV(1 + b);   // K buffer b full
        }
    }

    __syncthreads();
    if (tid < 128) {
        float mn = fminf(sMin[tid][0], sMin[tid][1]);
        float mx = fmaxf(sMax[tid][0], sMax[tid][1]);
        int row = (qt << 7) + tid;
        g_pmin[(((bh << 10) + row) << 1) + half] = mn;
        g_pmax[(((bh << 10) + row) << 1) + half] = mx;
    }
}

// ---------------------------------------------------------------------------
// K2: reduce 2 partials/row -> mn = sqrt(min m2), inv = 1/(mx - mn).
// ---------------------------------------------------------------------------
__global__ void minmax_kernel()
{
    int r = blockIdx.x * 256 + threadIdx.x;   // 65536 rows
    float mn2 = fminf(g_pmin[r * 2], g_pmin[r * 2 + 1]);
    float mx2 = fmaxf(g_pmax[r * 2], g_pmax[r * 2 + 1]);
    float mnv = sqrtf(mn2), mxv = sqrtf(mx2);
    g_mn[r] = mnv;
    g_inv[r] = 1.0f / (mxv - mnv);
}

// ---------------------------------------------------------------------------
// K3: AV. CTA tile 64q x 64d; 16 k-chunks of 64, A+V double-buffered.
// Consumers: 8 warps (4m x 2n), warp tile 16q x 32d (mb=1).
// Producers: normalize+split A chunk, split V chunk.
// out_r = ar.vr - ai.vi ; out_i = ar.vi + ai.vr
// ---------------------------------------------------------------------------
__global__ __launch_bounds__(384, 1) void av_kernel(
    const float* __restrict__ vr, const float* __restrict__ vi,
    float* __restrict__ out)
{
    extern __shared__ __align__(128) char sm[];
    // buffer b at sm + b*65536: A arrays arh,arl,aih,ail (4x8KB), then
    // V arrays vrh,vrl,vih,vil (4x8KB).
    __shared__ float smn[64], sinv[64];

    const int tid = threadIdx.x, wid = tid >> 5, lane = tid & 31;
    const int qt = blockIdx.x, bh = blockIdx.y;

    if (tid < 64) {
        int r = (bh << 10) + (qt << 6) + tid;
        float mnv = g_mn[r], invv = g_inv[r];
        sinv[tid] = invv;
        smn[tid] = mnv * invv;   // pre-multiplied
    }
    __syncthreads();

    if (wid < 8) {
        // ================= CONSUMERS =================
        const int wm = wid >> 1, wn = wid & 1;
        const int g = lane >> 2, tg = lane & 3;
        const u32 a_row = (u32)(wm * 16 + (lane & 15));
        const u32 a_cb  = (u32)((lane >> 4) * 16);
        const u32 bt_row = (u32)(lane & 15);
        const u32 bt_cb  = (u32)(wn * 64);

        float accR[4][4] = {}, accI[4][4] = {};

        #pragma unroll 1
        for (int c = 0; c < 16; ++c) {
            const int b = c & 1;
            BARSYNC(1 + b);
            const u32 ua = smem_u32(sm + b * 65536);
            const u32 uv = ua + 4 * TB8;

            #pragma unroll
            for (int kb = 0; kb < 4; ++kb) {
                u32 Aarh[4], Aarl[4], Aaih[4], Aail[4];
                {
                    u32 off = SW128(a_row * 128 + kb * 32 + a_cb);
                    ldmx4(Aarh, ua + off);
                    ldmx4(Aarl, ua + TB8 + off);
                    ldmx4(Aaih, ua + 2 * TB8 + off);
                    ldmx4(Aail, ua + 3 * TB8 + off);
                }
                #pragma unroll
                for (int nb = 0; nb < 4; ++nb) {
                    u32 off = SW128((bt_row + kb * 16) * 128 + bt_cb + nb * 16);
                    u32 Bvrh[2], Bvrl[2], Bvih[2], Bvil[2];
                    ldmx2t(Bvrh, uv + off);
                    ldmx2t(Bvrl, uv + TB8 + off);
                    ldmx2t(Bvih, uv + 2 * TB8 + off);
                    ldmx2t(Bvil, uv + 3 * TB8 + off);
                    u32 Bvnh[2] = { Bvih[0] ^ NEGS, Bvih[1] ^ NEGS };
                    u32 Bvnl[2] = { Bvil[0] ^ NEGS, Bvil[1] ^ NEGS };
                    mma16816(accR[nb], Aarh, Bvrh);
                    mma16816(accR[nb], Aarh, Bvrl);
                    mma16816(accR[nb], Aarl, Bvrh);
                    mma16816(accR[nb], Aaih, Bvnh);
                    mma16816(accR[nb], Aaih, Bvnl);
                    mma16816(accR[nb], Aail, Bvnh);
                    mma16816(accI[nb], Aarh, Bvih);
                    mma16816(accI[nb], Aarh, Bvil);
                    mma16816(accI[nb], Aarl, Bvih);
                    mma16816(accI[nb], Aaih, Bvrh);
                    mma16816(accI[nb], Aaih, Bvrl);
                    mma16816(accI[nb], Aail, Bvrh);
                }
            }
            BARARV(3 + b);
        }

        // epilogue: out[2][64][1024][64], imag at +4194304
        #pragma unroll
        for (int hf = 0; hf < 2; ++hf) {
            int row = (qt << 6) + wm * 16 + hf * 8 + g;
            size_t ob = ((size_t)((bh << 10) + row) << 6) + wn * 32 + tg * 2;
            #pragma unroll
            for (int nb = 0; nb < 4; ++nb) {
                *(float2*)(out + ob + nb * 8) =
                    make_float2(accR[nb][hf * 2], accR[nb][hf * 2 + 1]);
                *(float2*)(out + ob + nb * 8 + 4194304) =
                    make_float2(accI[nb][hf * 2], accI[nb][hf * 2 + 1]);
            }
        }
    } else {
        // ================= PRODUCERS =================
        const int ptid = tid - 256;
        const int cp = ptid & 31, r0 = ptid >> 5;
        const size_t abase = ((size_t)((bh << 10) + (qt << 6))) << 10;
        const size_t vbase = ((size_t)(bh << 10)) << 6;

        #pragma unroll 1
        for (int c = 0; c < 16; ++c) {
            const int b = c & 1;
            if (c >= 2) BARSYNC(3 + b);
            char* A = sm + b * 65536;
            char* V = A + 4 * TB8;
            // A: normalized attn [64q][64k]
            #pragma unroll
            for (int it = 0; it < 16; ++it) {
                int row = r0 + (it << 2);
                size_t ao = abase + ((size_t)row << 10) + (c << 6) + cp * 2;
                float2 a = *(const float2*)(g_ar + ao);
                float2 bb = *(const float2*)(g_ai + ao);
                float invv = sinv[row], mni = smn[row];
                float f0 = invv - mni * rsqrtf(a.x * a.x + bb.x * bb.x);
                float f1 = invv - mni * rsqrtf(a.y * a.y + bb.y * bb.y);
                float2 an = make_float2(a.x * f0, a.y * f1);
                float2 bn = make_float2(bb.x * f0, bb.y * f1);
                st_split2(A, A + TB8, row, cp, an);
                st_split2(A + 2 * TB8, A + 3 * TB8, row, cp, bn);
            }
            // V: natural [64k][64d]
            #pragma unroll
            for (int it = 0; it < 16; ++it) {
                int row = r0 + (it << 2);
                size_t vo = vbase + ((size_t)((c << 6) + row) << 6) + cp * 2;
                float2 x = *(const float2*)(vr + vo);
                float2 y = *(const float2*)(vi + vo);
                st_split2(V, V + TB8, row, cp, x);
                st_split2(V + 2 * TB8, V + 3 * TB8, row, cp, y);
            }
            BARARV(1 + b);
        }
    }
}

extern "C" void kernel_launch(void* const* d_in, const int* in_sizes, int n_in,
                              void* d_out, int out_size)
{
    (void)in_sizes; (void)n_in; (void)out_size;
    const float* qr = (const float*)d_in[0];
    const float* qi = (const float*)d_in[1];
    const float* kr = (const float*)d_in[2];
    const float* ki = (const float*)d_in[3];
    const float* vr = (const float*)d_in[4];
    const float* vi = (const float*)d_in[5];
    float* out = (float*)d_out;

    const int smem_qk = 4 * TB16 + 2 * 4 * TB8;   // 131072
    const int smem_av = 2 * 8 * TB8;               // 131072
    cudaFuncSetAttribute(qk_kernel, cudaFuncAttributeMaxDynamicSharedMemorySize, smem_qk);
    cudaFuncSetAttribute(av_kernel, cudaFuncAttributeMaxDynamicSharedMemorySize, smem_av);

    qk_kernel<<<dim3(2, 8, 64), 384, smem_qk>>>(qr, qi, kr, ki);
    minmax_kernel<<<256, 256>>>();
    av_kernel<<<dim3(16, 64), 384, smem_av>>>(vr, vi, out);
}